// round 2
// baseline (speedup 1.0000x reference)
#include <cuda_runtime.h>

// AudioOnlySpecAugment: out = concat(V, Aud * keep)
//   X: (32, 2048, 1536) fp32. V = X[..., :256] copied, Aud = X[..., 256:] masked.
//   keep[b,t,f] = !(tmask[b,t] | fmask[b,f])
// Pure streaming: ~805 MB traffic, HBM-bound.

#define B_N 32
#define T_N 2048
#define D_N 1536
#define A_N 1280
#define V_N 256
#define ROW_F4 (D_N / 4)   // 384 float4 per row

__global__ __launch_bounds__(ROW_F4) void spec_aug_kernel(
    const float4* __restrict__ X,
    const int*    __restrict__ len_words,  // raw 32-bit words of `lengths` (int32 or int64 storage)
    const float*  __restrict__ u_t,
    const float*  __restrict__ u_t0,
    const float*  __restrict__ u_f,
    const float*  __restrict__ u_f0,
    float4*       __restrict__ out)
{
    const int r = blockIdx.x;        // row index over B*T
    const int b = r >> 11;           // / 2048
    const int t = r & (T_N - 1);     // % 2048

    // --- dtype detection for `lengths` (warp-uniform, L1-resident) ---
    // Values are in [0, 2048). If stored as little-endian int64, every odd
    // 32-bit word is 0. If stored as int32, odd words are lengths[1],[3],...
    // (random in [0,2048), essentially surely not all zero). Words 1..31
    // stay within the first 128 bytes => in-bounds for both layouts.
    int odd_or = 0;
    #pragma unroll
    for (int i = 1; i < 32; i += 2) odd_or |= len_words[i];
    const int len = (odd_or == 0) ? len_words[2 * b] : len_words[b];

    // Time masks (NT = 2). Replicate reference f32 arithmetic exactly:
    //   max_t = floor(len * 0.2f); t_i = floor(u_t * (max_t + 1));
    //   rem = len - t_i; t0 = rem<=0 ? 0 : floor(u_t0 * (rem + 1))
    const float maxt = floorf((float)len * 0.2f);
    int tmask = 0;
    #pragma unroll
    for (int i = 0; i < 2; i++) {
        const int ti  = (int)floorf(u_t[i * B_N + b] * (maxt + 1.0f));
        const int rem = len - ti;
        const int t0  = (rem <= 0) ? 0
                        : (int)floorf(u_t0[i * B_N + b] * ((float)rem + 1.0f));
        tmask |= (int)((t >= t0) & (t < t0 + ti));
    }

    // Freq masks (NF = 2). max_f = int(1280 * 0.15) = 192.
    //   f_j = floor(u_f * 193); f0_max = max(1280 - f, 0);
    //   f0 = floor(u_f0 * (f0_max + 1))
    int f0a, f1a, f0b, f1b;
    {
        const int fA     = (int)floorf(u_f[0 * B_N + b] * 193.0f);
        int       f0maxA = A_N - fA; if (f0maxA < 0) f0maxA = 0;
        f0a = (int)floorf(u_f0[0 * B_N + b] * ((float)f0maxA + 1.0f));
        f1a = f0a + fA;

        const int fB     = (int)floorf(u_f[1 * B_N + b] * 193.0f);
        int       f0maxB = A_N - fB; if (f0maxB < 0) f0maxB = 0;
        f0b = (int)floorf(u_f0[1 * B_N + b] * ((float)f0maxB + 1.0f));
        f1b = f0b + fB;
    }

    const size_t idx = (size_t)r * ROW_F4 + threadIdx.x;
    const int d = threadIdx.x * 4;   // feature offset of this float4

    if (d < V_N) {
        // V region: straight copy
        out[idx] = X[idx];
    } else if (tmask) {
        // Whole audio region zeroed for this row: skip the read entirely
        out[idx] = make_float4(0.f, 0.f, 0.f, 0.f);
    } else {
        float4 v = X[idx];
        const int f = d - V_N;
        float* vp = reinterpret_cast<float*>(&v);
        #pragma unroll
        for (int c = 0; c < 4; c++) {
            const int fc = f + c;
            const bool m = (fc >= f0a && fc < f1a) || (fc >= f0b && fc < f1b);
            if (m) vp[c] = 0.0f;
        }
        out[idx] = v;
    }
}

extern "C" void kernel_launch(void* const* d_in, const int* in_sizes, int n_in,
                              void* d_out, int out_size)
{
    const float4* X    = (const float4*)d_in[0];
    const int*    lenw = (const int*)   d_in[1];   // raw words; layout auto-detected
    const float*  u_t  = (const float*) d_in[2];
    const float*  u_t0 = (const float*) d_in[3];
    const float*  u_f  = (const float*) d_in[4];
    const float*  u_f0 = (const float*) d_in[5];
    float4*       out  = (float4*)      d_out;

    const int rows = B_N * T_N;  // 65536
    spec_aug_kernel<<<rows, ROW_F4>>>(X, lenw, u_t, u_t0, u_f, u_f0, out);
}

// round 4
// speedup vs baseline: 1.1348x; 1.1348x over previous
#include <cuda_runtime.h>

// AudioOnlySpecAugment: out = concat(V, Aud * keep)
//   X: (32, 2048, 1536) fp32. V = X[..., :256] copied, Aud = X[..., 256:] masked.
// Two kernels: (1) per-batch mask windows -> __device__ params; (2) streaming apply.

#define B_N 32
#define T_N 2048
#define D_N 1536
#define A_N 1280
#define V_N 256
#define ROW_F4 (D_N / 4)   // 384 float4 per row
#define RPB 4              // rows per block (2048 % 4 == 0 -> same batch within block)

// [b][0..3] = t0a, t1a, t0b, t1b ; [b][4..7] = f0a, f1a, f0b, f1b
__device__ int g_params[B_N * 8];

__global__ void precompute_kernel(
    const int*   __restrict__ len_words,  // raw 32-bit words (int32 or int64 storage)
    const float* __restrict__ u_t,
    const float* __restrict__ u_t0,
    const float* __restrict__ u_f,
    const float* __restrict__ u_f0)
{
    const int b = threadIdx.x;
    if (b >= B_N) return;

    // dtype detection: values in [0,2048). int64-LE storage => all odd words 0.
    int odd_or = 0;
    #pragma unroll
    for (int i = 1; i < 32; i += 2) odd_or |= len_words[i];
    const int len = (odd_or == 0) ? len_words[2 * b] : len_words[b];

    // Time windows (NT=2), replicating reference f32 arithmetic exactly:
    //   max_t = floor(len*0.2f); t_i = floor(u_t*(max_t+1));
    //   rem = len - t_i; t0 = rem<=0 ? 0 : floor(u_t0*(rem+1)); window [t0, t0+t_i)
    const float maxt = floorf((float)len * 0.2f);
    #pragma unroll
    for (int i = 0; i < 2; i++) {
        const int ti  = (int)floorf(u_t[i * B_N + b] * (maxt + 1.0f));
        const int rem = len - ti;
        const int t0  = (rem <= 0) ? 0
                        : (int)floorf(u_t0[i * B_N + b] * ((float)rem + 1.0f));
        g_params[b * 8 + 2 * i]     = t0;
        g_params[b * 8 + 2 * i + 1] = t0 + ti;
    }

    // Freq windows (NF=2): max_f = int(1280*0.15) = 192.
    //   f = floor(u_f*193); f0_max = max(1280-f, 0); f0 = floor(u_f0*(f0_max+1))
    #pragma unroll
    for (int j = 0; j < 2; j++) {
        const int f     = (int)floorf(u_f[j * B_N + b] * 193.0f);
        int       f0max = A_N - f; if (f0max < 0) f0max = 0;
        const int f0 = (int)floorf(u_f0[j * B_N + b] * ((float)f0max + 1.0f));
        g_params[b * 8 + 4 + 2 * j]     = f0;
        g_params[b * 8 + 4 + 2 * j + 1] = f0 + f;
    }
}

__global__ __launch_bounds__(ROW_F4) void spec_aug_kernel(
    const float4* __restrict__ X,
    float4*       __restrict__ out)
{
    const int row0 = blockIdx.x * RPB;      // first row of this block
    const int b    = row0 >> 11;            // all RPB rows share this batch

    // Two uniform 16B loads: time windows + freq windows (L1-resident).
    const int4 tw = *reinterpret_cast<const int4*>(&g_params[b * 8]);
    const int4 fw = *reinterpret_cast<const int4*>(&g_params[b * 8 + 4]);

    const int tid = threadIdx.x;
    const int d   = tid * 4;                // feature offset of this float4
    const bool isV = (d < V_N);

    // Per-lane freq keep multiplier (row-invariant). out = Aud * keep, matching
    // the reference's multiply semantics exactly.
    float4 keep;
    {
        const int f = d - V_N;
        float* kp = reinterpret_cast<float*>(&keep);
        #pragma unroll
        for (int c = 0; c < 4; c++) {
            const int fc = f + c;
            const bool m = (fc >= fw.x && fc < fw.y) || (fc >= fw.z && fc < fw.w);
            kp[c] = m ? 0.0f : 1.0f;
        }
    }

    #pragma unroll
    for (int rr = 0; rr < RPB; rr++) {
        const int r = row0 + rr;
        const int t = r & (T_N - 1);
        const size_t idx = (size_t)r * ROW_F4 + tid;

        if (isV) {
            out[idx] = X[idx];
        } else if ((t >= tw.x && t < tw.y) || (t >= tw.z && t < tw.w)) {
            // whole audio region zeroed for this row: skip the read
            out[idx] = make_float4(0.f, 0.f, 0.f, 0.f);
        } else {
            float4 v = X[idx];
            v.x *= keep.x; v.y *= keep.y; v.z *= keep.z; v.w *= keep.w;
            out[idx] = v;
        }
    }
}

extern "C" void kernel_launch(void* const* d_in, const int* in_sizes, int n_in,
                              void* d_out, int out_size)
{
    const float4* X    = (const float4*)d_in[0];
    const int*    lenw = (const int*)   d_in[1];
    const float*  u_t  = (const float*) d_in[2];
    const float*  u_t0 = (const float*) d_in[3];
    const float*  u_f  = (const float*) d_in[4];
    const float*  u_f0 = (const float*) d_in[5];
    float4*       out  = (float4*)      d_out;

    precompute_kernel<<<1, B_N>>>(lenw, u_t, u_t0, u_f, u_f0);
    spec_aug_kernel<<<(B_N * T_N) / RPB, ROW_F4>>>(X, out);
}

// round 5
// speedup vs baseline: 1.2739x; 1.1226x over previous
#include <cuda_runtime.h>

// AudioOnlySpecAugment: out = concat(V, Aud * keep)
//   X: (32, 2048, 1536) fp32. V = X[..., :256] copied, Aud = X[..., 256:] masked.
// Two kernels: (1) per-batch mask windows -> __device__ params; (2) streaming apply.

#define B_N 32
#define T_N 2048
#define D_N 1536
#define A_N 1280
#define V_N 256
#define ROW_F4 (D_N / 4)   // 384 float4 per row
#define RPB 4              // rows per block (2048 % 4 == 0 -> same batch within block)

// [b][0..3] = t0a, t1a, t0b, t1b ; [b][4..7] = f0a, f1a, f0b, f1b
__device__ int g_params[B_N * 8];

__global__ void precompute_kernel(
    const int*   __restrict__ len_words,  // raw 32-bit words (int32 or int64 storage)
    const float* __restrict__ u_t,
    const float* __restrict__ u_t0,
    const float* __restrict__ u_f,
    const float* __restrict__ u_f0)
{
    const int b = threadIdx.x;
    if (b >= B_N) return;

    // dtype detection: values in [0,2048). int64-LE storage => all odd words 0.
    int odd_or = 0;
    #pragma unroll
    for (int i = 1; i < 32; i += 2) odd_or |= len_words[i];
    const int len = (odd_or == 0) ? len_words[2 * b] : len_words[b];

    // Time windows (NT=2), replicating reference f32 arithmetic exactly:
    //   max_t = floor(len*0.2f); t_i = floor(u_t*(max_t+1));
    //   rem = len - t_i; t0 = rem<=0 ? 0 : floor(u_t0*(rem+1)); window [t0, t0+t_i)
    const float maxt = floorf((float)len * 0.2f);
    #pragma unroll
    for (int i = 0; i < 2; i++) {
        const int ti  = (int)floorf(u_t[i * B_N + b] * (maxt + 1.0f));
        const int rem = len - ti;
        const int t0  = (rem <= 0) ? 0
                        : (int)floorf(u_t0[i * B_N + b] * ((float)rem + 1.0f));
        g_params[b * 8 + 2 * i]     = t0;
        g_params[b * 8 + 2 * i + 1] = t0 + ti;
    }

    // Freq windows (NF=2): max_f = int(1280*0.15) = 192.
    //   f = floor(u_f*193); f0_max = max(1280-f, 0); f0 = floor(u_f0*(f0_max+1))
    #pragma unroll
    for (int j = 0; j < 2; j++) {
        const int f     = (int)floorf(u_f[j * B_N + b] * 193.0f);
        int       f0max = A_N - f; if (f0max < 0) f0max = 0;
        const int f0 = (int)floorf(u_f0[j * B_N + b] * ((float)f0max + 1.0f));
        g_params[b * 8 + 4 + 2 * j]     = f0;
        g_params[b * 8 + 4 + 2 * j + 1] = f0 + f;
    }
}

__global__ __launch_bounds__(ROW_F4) void spec_aug_kernel(
    const float4* __restrict__ X,
    float4*       __restrict__ out)
{
    const int row0 = blockIdx.x * RPB;      // first row of this block
    const int b    = row0 >> 11;            // all RPB rows share this batch
    const int t0r  = row0 & (T_N - 1);      // t of first row

    // Two uniform 16B loads: time windows + freq windows (L1-resident).
    const int4 tw = *reinterpret_cast<const int4*>(&g_params[b * 8]);
    const int4 fw = *reinterpret_cast<const int4*>(&g_params[b * 8 + 4]);

    const int tid = threadIdx.x;
    const int d   = tid * 4;                // feature offset of this float4
    const bool isV = (d < V_N);

    // Per-lane freq keep multiplier (row-invariant). out = Aud * keep, matching
    // the reference's multiply semantics exactly. V region: keep = 1.
    float4 keep;
    {
        const int f = d - V_N;
        float* kp = reinterpret_cast<float*>(&keep);
        #pragma unroll
        for (int c = 0; c < 4; c++) {
            const int fc = f + c;
            const bool m = !isV &&
                ((fc >= fw.x && fc < fw.y) || (fc >= fw.z && fc < fw.w));
            kp[c] = m ? 0.0f : 1.0f;
        }
    }

    // Per-row time mask, and whether this lane writes zeros for masked rows.
    bool zrow[RPB];
    #pragma unroll
    for (int rr = 0; rr < RPB; rr++) {
        const int t = t0r + rr;
        zrow[rr] = !isV && ((t >= tw.x && t < tw.y) || (t >= tw.z && t < tw.w));
    }

    const float4* ip = X   + (size_t)row0 * ROW_F4 + tid;
    float4*       op = out + (size_t)row0 * ROW_F4 + tid;

    // Load-all: issue the (up to) 4 LDG.128 back-to-back for full MLP.
    float4 v[RPB];
    #pragma unroll
    for (int rr = 0; rr < RPB; rr++) {
        if (!zrow[rr]) v[rr] = __ldcs(ip + rr * ROW_F4);
    }

    // Mask + store-all.
    #pragma unroll
    for (int rr = 0; rr < RPB; rr++) {
        float4 w;
        if (zrow[rr]) {
            w = make_float4(0.f, 0.f, 0.f, 0.f);
        } else {
            w.x = v[rr].x * keep.x;
            w.y = v[rr].y * keep.y;
            w.z = v[rr].z * keep.z;
            w.w = v[rr].w * keep.w;
        }
        __stcs(op + rr * ROW_F4, w);
    }
}

extern "C" void kernel_launch(void* const* d_in, const int* in_sizes, int n_in,
                              void* d_out, int out_size)
{
    const float4* X    = (const float4*)d_in[0];
    const int*    lenw = (const int*)   d_in[1];
    const float*  u_t  = (const float*) d_in[2];
    const float*  u_t0 = (const float*) d_in[3];
    const float*  u_f  = (const float*) d_in[4];
    const float*  u_f0 = (const float*) d_in[5];
    float4*       out  = (float4*)      d_out;

    precompute_kernel<<<1, B_N>>>(lenw, u_t, u_t0, u_f, u_f0);
    spec_aug_kernel<<<(B_N * T_N) / RPB, ROW_F4>>>(X, out);
}

// round 6
// speedup vs baseline: 1.2795x; 1.0044x over previous
#include <cuda_runtime.h>

// AudioOnlySpecAugment: out = concat(V, Aud * keep)
//   X: (32, 2048, 1536) fp32. V = X[..., :256] copied, Aud = X[..., 256:] masked.
// Single fused kernel: thread 0 of each block derives the per-batch mask windows
// (cheap, L1-resident), broadcast via shared; body is a pure streaming copy+mask.

#define B_N 32
#define T_N 2048
#define D_N 1536
#define A_N 1280
#define V_N 256
#define ROW_F4 (D_N / 4)   // 384 float4 per row
#define RPB 4              // rows per block (2048 % 4 == 0 -> same batch within block)

__global__ __launch_bounds__(ROW_F4) void spec_aug_kernel(
    const float4* __restrict__ X,
    const int*    __restrict__ len_words,  // raw 32-bit words (int32 or int64 storage)
    const float*  __restrict__ u_t,
    const float*  __restrict__ u_t0,
    const float*  __restrict__ u_f,
    const float*  __restrict__ u_f0,
    float4*       __restrict__ out)
{
    __shared__ int s_p[8];   // t0a,t1a,t0b,t1b, f0a,f1a,f0b,f1b

    const int row0 = blockIdx.x * RPB;      // first row of this block
    const int b    = row0 >> 11;            // all RPB rows share this batch
    const int t0r  = row0 & (T_N - 1);      // t of first row
    const int tid  = threadIdx.x;

    if (tid == 0) {
        // dtype detection for `lengths`: values in [0,2048). int64-LE storage
        // => every odd 32-bit word is 0; int32 => odd words ~surely nonzero.
        // Words 1..31 stay within first 128B, in-bounds for both layouts.
        int odd_or = 0;
        #pragma unroll
        for (int i = 1; i < 32; i += 2) odd_or |= len_words[i];
        const int len = (odd_or == 0) ? len_words[2 * b] : len_words[b];

        // Time windows (NT=2), replicating reference f32 arithmetic exactly:
        //   max_t = floor(len*0.2f); t_i = floor(u_t*(max_t+1));
        //   rem = len - t_i; t0 = rem<=0 ? 0 : floor(u_t0*(rem+1))
        const float maxt = floorf((float)len * 0.2f);
        #pragma unroll
        for (int i = 0; i < 2; i++) {
            const int ti  = (int)floorf(u_t[i * B_N + b] * (maxt + 1.0f));
            const int rem = len - ti;
            const int t0  = (rem <= 0) ? 0
                            : (int)floorf(u_t0[i * B_N + b] * ((float)rem + 1.0f));
            s_p[2 * i]     = t0;
            s_p[2 * i + 1] = t0 + ti;
        }

        // Freq windows (NF=2): max_f = int(1280*0.15) = 192.
        //   f = floor(u_f*193); f0_max = max(1280-f,0); f0 = floor(u_f0*(f0_max+1))
        #pragma unroll
        for (int j = 0; j < 2; j++) {
            const int f     = (int)floorf(u_f[j * B_N + b] * 193.0f);
            int       f0max = A_N - f; if (f0max < 0) f0max = 0;
            const int f0 = (int)floorf(u_f0[j * B_N + b] * ((float)f0max + 1.0f));
            s_p[4 + 2 * j]     = f0;
            s_p[4 + 2 * j + 1] = f0 + f;
        }
    }
    __syncthreads();

    const int4 tw = *reinterpret_cast<const int4*>(&s_p[0]);
    const int4 fw = *reinterpret_cast<const int4*>(&s_p[4]);

    const int d   = tid * 4;                // feature offset of this float4
    const bool isV = (d < V_N);

    // Per-lane freq keep multiplier (row-invariant). out = Aud * keep, matching
    // the reference's multiply semantics exactly. V region: keep = 1.
    float4 keep;
    {
        const int f = d - V_N;
        float* kp = reinterpret_cast<float*>(&keep);
        #pragma unroll
        for (int c = 0; c < 4; c++) {
            const int fc = f + c;
            const bool m = !isV &&
                ((fc >= fw.x && fc < fw.y) || (fc >= fw.z && fc < fw.w));
            kp[c] = m ? 0.0f : 1.0f;
        }
    }

    // Per-row time mask: masked rows write zeros (audio lanes), skip the read.
    bool zrow[RPB];
    #pragma unroll
    for (int rr = 0; rr < RPB; rr++) {
        const int t = t0r + rr;
        zrow[rr] = !isV && ((t >= tw.x && t < tw.y) || (t >= tw.z && t < tw.w));
    }

    const float4* ip = X   + (size_t)row0 * ROW_F4 + tid;
    float4*       op = out + (size_t)row0 * ROW_F4 + tid;

    // Load-all: issue the (up to) 4 LDG.128 back-to-back for full MLP.
    float4 v[RPB];
    #pragma unroll
    for (int rr = 0; rr < RPB; rr++) {
        if (!zrow[rr]) v[rr] = __ldcs(ip + rr * ROW_F4);
    }

    // Mask + store-all.
    #pragma unroll
    for (int rr = 0; rr < RPB; rr++) {
        float4 w;
        if (zrow[rr]) {
            w = make_float4(0.f, 0.f, 0.f, 0.f);
        } else {
            w.x = v[rr].x * keep.x;
            w.y = v[rr].y * keep.y;
            w.z = v[rr].z * keep.z;
            w.w = v[rr].w * keep.w;
        }
        __stcs(op + rr * ROW_F4, w);
    }
}

extern "C" void kernel_launch(void* const* d_in, const int* in_sizes, int n_in,
                              void* d_out, int out_size)
{
    const float4* X    = (const float4*)d_in[0];
    const int*    lenw = (const int*)   d_in[1];
    const float*  u_t  = (const float*) d_in[2];
    const float*  u_t0 = (const float*) d_in[3];
    const float*  u_f  = (const float*) d_in[4];
    const float*  u_f0 = (const float*) d_in[5];
    float4*       out  = (float4*)      d_out;

    spec_aug_kernel<<<(B_N * T_N) / RPB, ROW_F4>>>(X, lenw, u_t, u_t0, u_f, u_f0, out);
}

// round 7
// speedup vs baseline: 1.3268x; 1.0370x over previous
#include <cuda_runtime.h>

// AudioOnlySpecAugment: out = concat(V, Aud * keep)
//   X: (32, 2048, 1536) fp32. V = X[..., :256] copied, Aud = X[..., 256:] masked.
// Single fused kernel: thread 0 of each block derives the per-batch mask windows
// (cheap, L1-resident), broadcast via shared; body is a pure streaming copy+mask.
// Reads are skipped for time-masked rows AND freq-masked lanes (output is zero
// there either way; X is finite so v*0 == 0 matches the reference product).

#define B_N 32
#define T_N 2048
#define D_N 1536
#define A_N 1280
#define V_N 256
#define ROW_F4 (D_N / 4)   // 384 float4 per row
#define RPB 4              // rows per block (2048 % 4 == 0 -> same batch within block)

__global__ __launch_bounds__(ROW_F4) void spec_aug_kernel(
    const float4* __restrict__ X,
    const int*    __restrict__ len_words,  // raw 32-bit words (int32 or int64 storage)
    const float*  __restrict__ u_t,
    const float*  __restrict__ u_t0,
    const float*  __restrict__ u_f,
    const float*  __restrict__ u_f0,
    float4*       __restrict__ out)
{
    __shared__ int s_p[8];   // t0a,t1a,t0b,t1b, f0a,f1a,f0b,f1b

    const int row0 = blockIdx.x * RPB;      // first row of this block
    const int b    = row0 >> 11;            // all RPB rows share this batch
    const int t0r  = row0 & (T_N - 1);      // t of first row
    const int tid  = threadIdx.x;

    if (tid == 0) {
        // dtype detection for `lengths`: values in [0,2048). int64-LE storage
        // => every odd 32-bit word is 0; int32 => odd words ~surely nonzero
        // (P[all 4 zero] ~ 6e-14). Words 1..15 in-bounds for both layouts.
        int odd_or = 0;
        #pragma unroll
        for (int i = 1; i < 16; i += 2) odd_or |= len_words[i];
        const int len = (odd_or == 0) ? len_words[2 * b] : len_words[b];

        // Time windows (NT=2), replicating reference f32 arithmetic exactly:
        //   max_t = floor(len*0.2f); t_i = floor(u_t*(max_t+1));
        //   rem = len - t_i; t0 = rem<=0 ? 0 : floor(u_t0*(rem+1))
        const float maxt = floorf((float)len * 0.2f);
        #pragma unroll
        for (int i = 0; i < 2; i++) {
            const int ti  = (int)floorf(u_t[i * B_N + b] * (maxt + 1.0f));
            const int rem = len - ti;
            const int t0  = (rem <= 0) ? 0
                            : (int)floorf(u_t0[i * B_N + b] * ((float)rem + 1.0f));
            s_p[2 * i]     = t0;
            s_p[2 * i + 1] = t0 + ti;
        }

        // Freq windows (NF=2): max_f = int(1280*0.15) = 192.
        //   f = floor(u_f*193); f0_max = max(1280-f,0); f0 = floor(u_f0*(f0_max+1))
        #pragma unroll
        for (int j = 0; j < 2; j++) {
            const int f     = (int)floorf(u_f[j * B_N + b] * 193.0f);
            int       f0max = A_N - f; if (f0max < 0) f0max = 0;
            const int f0 = (int)floorf(u_f0[j * B_N + b] * ((float)f0max + 1.0f));
            s_p[4 + 2 * j]     = f0;
            s_p[4 + 2 * j + 1] = f0 + f;
        }
    }
    __syncthreads();

    const int4 tw = *reinterpret_cast<const int4*>(&s_p[0]);
    const int4 fw = *reinterpret_cast<const int4*>(&s_p[4]);

    const int d   = tid * 4;                // feature offset of this float4
    const bool isV = (d < V_N);

    // Per-lane freq keep multiplier (row-invariant). V region: keep = 1.
    float4 keep;
    {
        const int f = d - V_N;
        float* kp = reinterpret_cast<float*>(&keep);
        #pragma unroll
        for (int c = 0; c < 4; c++) {
            const int fc = f + c;
            const bool m = !isV &&
                ((fc >= fw.x && fc < fw.y) || (fc >= fw.z && fc < fw.w));
            kp[c] = m ? 0.0f : 1.0f;
        }
    }
    // Lane fully freq-masked -> its 32B sector is never needed.
    const bool kz = (keep.x == 0.0f) & (keep.y == 0.0f) &
                    (keep.z == 0.0f) & (keep.w == 0.0f);

    // Per-row time mask: masked rows (audio lanes) write zeros, skip the read.
    bool zrow[RPB];
    #pragma unroll
    for (int rr = 0; rr < RPB; rr++) {
        const int t = t0r + rr;
        zrow[rr] = !isV && ((t >= tw.x && t < tw.y) || (t >= tw.z && t < tw.w));
    }

    const float4* ip = X   + (size_t)row0 * ROW_F4 + tid;
    float4*       op = out + (size_t)row0 * ROW_F4 + tid;

    // Load-all: issue the needed LDG.128 back-to-back for full MLP.
    float4 v[RPB];
    #pragma unroll
    for (int rr = 0; rr < RPB; rr++) {
        if (!zrow[rr] && !kz) v[rr] = __ldcs(ip + rr * ROW_F4);
    }

    // Mask + store-all.
    #pragma unroll
    for (int rr = 0; rr < RPB; rr++) {
        float4 w;
        if (zrow[rr] || kz) {
            w = make_float4(0.f, 0.f, 0.f, 0.f);
        } else {
            w.x = v[rr].x * keep.x;
            w.y = v[rr].y * keep.y;
            w.z = v[rr].z * keep.z;
            w.w = v[rr].w * keep.w;
        }
        __stcs(op + rr * ROW_F4, w);
    }
}

extern "C" void kernel_launch(void* const* d_in, const int* in_sizes, int n_in,
                              void* d_out, int out_size)
{
    const float4* X    = (const float4*)d_in[0];
    const int*    lenw = (const int*)   d_in[1];
    const float*  u_t  = (const float*) d_in[2];
    const float*  u_t0 = (const float*) d_in[3];
    const float*  u_f  = (const float*) d_in[4];
    const float*  u_f0 = (const float*) d_in[5];
    float4*       out  = (float4*)      d_out;

    spec_aug_kernel<<<(B_N * T_N) / RPB, ROW_F4>>>(X, lenw, u_t, u_t0, u_f, u_f0, out);
}